// round 4
// baseline (speedup 1.0000x reference)
#include <cuda_runtime.h>
#include <math.h>

#define SOSID 2
#define EPSF  1e-6f

typedef unsigned long long u64;

// ---------------- persistent device state ----------------
__device__ float g_phi_hs[3200*512];   // tanh(enc @ Wh + bh), rows = b*100+l
__device__ float g_phi_fds[3200*512];  // tanh(field @ Wf + bf)
__device__ float g_zx[2080*2048];      // x_t @ lstm_W[0:512] + lstm_b, rows = t*32+b
__device__ float g_hbuf[2][32*512];
__device__ float g_cbuf[2][32*512];
__device__ float g_ot[32*512];
__device__ float g_gamma[32*512];
__device__ float g_alpha[32*512];
__device__ float g_ctx[32*512];
__device__ float g_att[32*512];

// ---------------- f32x2 helpers ----------------
__device__ __forceinline__ u64 pk2(float lo, float hi){
    u64 r; asm("mov.b64 %0, {%1,%2};" : "=l"(r) : "f"(lo), "f"(hi)); return r;
}
__device__ __forceinline__ void upk2(u64 v, float& lo, float& hi){
    asm("mov.b64 {%0,%1}, %2;" : "=f"(lo), "=f"(hi) : "l"(v));
}
__device__ __forceinline__ u64 ffma2(u64 a, u64 b, u64 c){
    u64 r; asm("fma.rn.f32x2 %0, %1, %2, %3;" : "=l"(r) : "l"(a), "l"(b), "l"(c)); return r;
}
__device__ __forceinline__ u64 fadd2(u64 a, u64 b){
    u64 r; asm("add.rn.f32x2 %0, %1, %2;" : "=l"(r) : "l"(a), "l"(b)); return r;
}
__device__ __forceinline__ float sigf(float x){ return 1.f/(1.f+expf(-x)); }

// ---------------- generic M=32 GEMM ----------------
// C[32 x cols] = A[32 x K] @ W[K x cols]  (+ epilogue)
// Thread decomposition: cg (4 cols), rh (16 rows as 8 row-pairs), ks (K-split).
// A kept transposed in smem with row-pairs adjacent -> LDS.64 == f32x2 operand.
//
// AMODE: 0 = external A[row*lda+k]   1 = ZX x-gather (A=embedding, p1=input_emb)
//        2 = concat(ctx|ot)   3 = g_hbuf[t&1]   4 = g_ot   5 = g_att
// GATED: thread's 4 cols are the 4 LSTM gates of one h (stride 512 in W)
// EPI:   0 phi_hs   1 phi_fds   2 zx(+bias)   3 lstm gates/state
//        4 gamma/alpha (blockIdx.y selects)   5 att(tanh+mask)   6 logits
template<int K, int NT, int KS, int AMODE, int GATED, int EPI>
__global__ void __launch_bounds__(2*(NT/4)*KS)
g32(const float* __restrict__ W, const float* __restrict__ Bv,
    const float* __restrict__ A, int lda,
    float* __restrict__ out,
    int ldw, int t, const int* __restrict__ lens,
    const float* __restrict__ p0, const float* __restrict__ p1)
{
    constexpr int CG  = NT/4;
    constexpr int TH  = 2*CG*KS;
    constexpr int ATS = 36;            // padded smem row stride (floats)
    extern __shared__ float sm[];
    float* at = sm;                    // A^T : at[k*ATS + m]
    u64*  red = (u64*)(sm + K*ATS);

    const int tid = threadIdx.x;
    const int cg  = tid % CG;
    const int rh  = (tid / CG) & 1;
    const int ks  = tid / (2*CG);
    const int rowBase = (EPI<=2) ? (int)blockIdx.y*32 : 0;

    const float* Wl = W; const float* Bl = Bv;
    if (EPI==4 && blockIdx.y==1){ Wl = p0; Bl = p1; }

    // load A^T (k fast-varying across threads -> coalesced gmem reads)
    for (int idx = tid; idx < 32*K; idx += TH) {
        int m = idx / K, k = idx - m*K;
        float v;
        if (AMODE==0)      v = A[(size_t)(rowBase+m)*lda + k];
        else if (AMODE==1) { int tt = blockIdx.y;
                             v = (tt==0) ? A[SOSID*512 + k]
                                         : p1[((size_t)m*64 + (tt-1))*512 + k]; }
        else if (AMODE==2) v = (k<512) ? g_ctx[m*512+k] : g_ot[m*512+k-512];
        else if (AMODE==3) v = g_hbuf[t&1][m*512+k];
        else if (AMODE==4) v = g_ot[m*512+k];
        else               v = g_att[m*512+k];
        at[k*ATS + m] = v;
    }
    __syncthreads();

    u64 acc[8][4];
    #pragma unroll
    for (int i=0;i<8;i++){ acc[i][0]=0; acc[i][1]=0; acc[i][2]=0; acc[i][3]=0; }

    const int k0 = ks*(K/KS);
    const float* wp;
    if (GATED) wp = Wl + (size_t)k0*ldw + (size_t)blockIdx.x*CG + cg;
    else       wp = Wl + (size_t)k0*ldw + (size_t)blockIdx.x*NT + cg*4;
    const float* ap = at + k0*ATS + rh*16;

    #pragma unroll 4
    for (int kk=0; kk<K/KS; kk++) {
        u64 b0,b1,b2,b3;
        if (GATED) {
            float w0=wp[0], w1=wp[512], w2=wp[1024], w3=wp[1536];
            b0=pk2(w0,w0); b1=pk2(w1,w1); b2=pk2(w2,w2); b3=pk2(w3,w3);
        } else {
            float4 w4 = *(const float4*)wp;
            b0=pk2(w4.x,w4.x); b1=pk2(w4.y,w4.y); b2=pk2(w4.z,w4.z); b3=pk2(w4.w,w4.w);
        }
        wp += ldw;
        u64 aa[8];
        #pragma unroll
        for (int i=0;i<8;i++) aa[i] = ((const u64*)ap)[i];
        ap += ATS;
        #pragma unroll
        for (int m2=0;m2<8;m2++){
            acc[m2][0]=ffma2(aa[m2],b0,acc[m2][0]);
            acc[m2][1]=ffma2(aa[m2],b1,acc[m2][1]);
            acc[m2][2]=ffma2(aa[m2],b2,acc[m2][2]);
            acc[m2][3]=ffma2(aa[m2],b3,acc[m2][3]);
        }
    }

    // K-split tree reduction in smem
    if (KS>1) {
        u64* mr = red + (size_t)tid*33;
        #pragma unroll
        for (int m2=0;m2<8;m2++){
            mr[4*m2+0]=acc[m2][0]; mr[4*m2+1]=acc[m2][1];
            mr[4*m2+2]=acc[m2][2]; mr[4*m2+3]=acc[m2][3];
        }
        __syncthreads();
        for (int s=KS/2; s>=1; s>>=1){
            if (ks < s){
                const u64* pr = mr + (size_t)(s*2*CG)*33;
                #pragma unroll
                for (int m2=0;m2<8;m2++){
                    acc[m2][0]=fadd2(acc[m2][0],pr[4*m2+0]);
                    acc[m2][1]=fadd2(acc[m2][1],pr[4*m2+1]);
                    acc[m2][2]=fadd2(acc[m2][2],pr[4*m2+2]);
                    acc[m2][3]=fadd2(acc[m2][3],pr[4*m2+3]);
                }
                if (s>1){
                    #pragma unroll
                    for (int m2=0;m2<8;m2++){
                        mr[4*m2+0]=acc[m2][0]; mr[4*m2+1]=acc[m2][1];
                        mr[4*m2+2]=acc[m2][2]; mr[4*m2+3]=acc[m2][3];
                    }
                }
            }
            __syncthreads();
        }
    }
    if (ks) return;

    // ---------------- epilogues ----------------
    if (EPI==3) {                                   // LSTM gates + state update
        int h  = blockIdx.x*CG + cg;
        int pb = t&1, cb = pb^1;
        #pragma unroll
        for (int m2=0;m2<8;m2++){
            float zi[2],zj[2],zf[2],zo[2];
            upk2(acc[m2][0],zi[0],zi[1]); upk2(acc[m2][1],zj[0],zj[1]);
            upk2(acc[m2][2],zf[0],zf[1]); upk2(acc[m2][3],zo[0],zo[1]);
            #pragma unroll
            for (int r=0;r<2;r++){
                int b = rh*16 + 2*m2 + r;
                const float* zxp = g_zx + ((size_t)(t*32+b))*2048 + h;
                float vi = zi[r] + zxp[0];
                float vj = zj[r] + zxp[512];
                float vf = zf[r] + zxp[1024];
                float vo = zo[r] + zxp[1536];
                float cp = g_cbuf[pb][b*512+h];
                float hp = g_hbuf[pb][b*512+h];
                float cn = sigf(vf+1.f)*cp + sigf(vi)*tanhf(vj);
                float hn = sigf(vo)*tanhf(cn);
                bool fin = (t>0) && (t-1 >= lens[b]);
                g_ot[b*512+h]       = fin ? 0.f : hn;
                g_hbuf[cb][b*512+h] = fin ? hp  : hn;
                g_cbuf[cb][b*512+h] = fin ? cp  : cn;
            }
        }
    } else {
        int c0 = blockIdx.x*NT + cg*4;
        #pragma unroll
        for (int m2=0;m2<8;m2++){
            float v0[4], v1[4];
            upk2(acc[m2][0],v0[0],v1[0]); upk2(acc[m2][1],v0[1],v1[1]);
            upk2(acc[m2][2],v0[2],v1[2]); upk2(acc[m2][3],v0[3],v1[3]);
            #pragma unroll
            for (int r=0;r<2;r++){
                int row = rowBase + rh*16 + 2*m2 + r;
                const float* vv = r ? v1 : v0;
                #pragma unroll
                for (int j=0;j<4;j++){
                    int c = c0 + j;
                    float x = vv[j] + Bl[c];
                    if (EPI==0)      g_phi_hs [(size_t)row*512 +c] = tanhf(x);
                    else if (EPI==1) g_phi_fds[(size_t)row*512 +c] = tanhf(x);
                    else if (EPI==2) g_zx     [(size_t)row*2048+c] = x;
                    else if (EPI==4) { float y = tanhf(x);
                                       if (blockIdx.y) g_alpha[row*512+c]=y;
                                       else            g_gamma[row*512+c]=y; }
                    else if (EPI==5) { bool fin=(t>0)&&(t-1>=lens[row]);
                                       g_att[row*512+c] = fin?0.f:tanhf(x); }
                    else /*6*/       { bool fin=(t>0)&&(t-1>=lens[row]);
                                       out[(size_t)row*2080000 + (size_t)t*32000 + c] = fin?0.f:x; }
                }
            }
        }
    }
}

// ---------------- attention: scores + softmaxes + context ----------------
__global__ void attn_kernel(const float* __restrict__ enc)
{
    int b = blockIdx.x;
    __shared__ float sg[512], sa[512], sh[100], sf[100], sw[100];
    __shared__ float ssum[2], wden;
    int tid = threadIdx.x, warp = tid>>5, lane = tid&31;

    for (int i=tid;i<512;i+=256){ sg[i]=g_gamma[b*512+i]; sa[i]=g_alpha[b*512+i]; }
    __syncthreads();

    for (int l = warp; l < 100; l += 8) {
        const float* ph = g_phi_hs  + ((size_t)b*100 + l)*512;
        const float* pf = g_phi_fds + ((size_t)b*100 + l)*512;
        float s1=0.f, s2=0.f;
        for (int k=lane;k<512;k+=32){ s1 += ph[k]*sg[k]; s2 += pf[k]*sa[k]; }
        #pragma unroll
        for (int o=16;o;o>>=1){ s1 += __shfl_xor_sync(~0u,s1,o); s2 += __shfl_xor_sync(~0u,s2,o); }
        if (lane==0){ sh[l]=s1; sf[l]=s2; }
    }
    __syncthreads();

    if (warp<2) {                       // two softmaxes in parallel
        float* s = warp ? sf : sh;
        float mx=-1e30f;
        for (int l=lane;l<100;l+=32) mx = fmaxf(mx, s[l]);
        #pragma unroll
        for (int o=16;o;o>>=1) mx = fmaxf(mx, __shfl_xor_sync(~0u,mx,o));
        float sum=0.f;
        for (int l=lane;l<100;l+=32){ float e = expf(s[l]-mx); s[l]=e; sum+=e; }
        #pragma unroll
        for (int o=16;o;o>>=1) sum += __shfl_xor_sync(~0u,sum,o);
        if (lane==0) ssum[warp] = EPSF + sum;
    }
    __syncthreads();

    if (warp==0){
        float d1 = ssum[0], d2 = ssum[1];
        float wsum = 0.f;
        for (int l=lane;l<100;l+=32){ float w = (sh[l]/d1)*(sf[l]/d2); sw[l]=w; wsum += w; }
        #pragma unroll
        for (int o=16;o;o>>=1) wsum += __shfl_xor_sync(~0u,wsum,o);
        if (lane==0) wden = EPSF + wsum;
    }
    __syncthreads();
    if (warp==0) for (int l=lane;l<100;l+=32) sw[l] = sw[l]/wden;
    __syncthreads();

    for (int h = tid; h < 512; h += 256) {
        float c = 0.f;
        const float* e = enc + (size_t)b*100*512 + h;
        for (int l=0;l<100;l++) c += sw[l]*e[(size_t)l*512];
        g_ctx[b*512+h] = c;
    }
}

__global__ void finalize_kernel(float* __restrict__ out)
{
    int i = blockIdx.x*256 + threadIdx.x;
    if (i < 32*512){
        out[66560000 + i]         = g_hbuf[1][i];
        out[66560000 + 16384 + i] = g_cbuf[1][i];
    }
}

// ---------------- host ----------------
extern "C" void kernel_launch(void* const* d_in, const int* in_sizes, int n_in,
                              void* d_out, int out_size)
{
    const float* h0   = (const float*)d_in[0];
    const float* c0   = (const float*)d_in[1];
    const float* inp  = (const float*)d_in[2];   // (32,64,512)
    const float* enc  = (const float*)d_in[3];   // (32,100,512)
    const float* fld  = (const float*)d_in[4];   // (32,100,64)
    const float* emb  = (const float*)d_in[5];   // (32000,512)
    const float* lW   = (const float*)d_in[6];   // (1024,2048)
    const float* lb   = (const float*)d_in[7];
    const float* Wh   = (const float*)d_in[8];
    const float* bh   = (const float*)d_in[9];
    const float* Ws   = (const float*)d_in[10];
    const float* bs   = (const float*)d_in[11];
    const float* Wr   = (const float*)d_in[12];
    const float* br   = (const float*)d_in[13];
    const float* Wf   = (const float*)d_in[14];
    const float* bf   = (const float*)d_in[15];
    const float* Wo   = (const float*)d_in[16];
    const float* bo   = (const float*)d_in[17];
    const float* oW   = (const float*)d_in[18];
    const float* ob   = (const float*)d_in[19];
    const int*   lens = (const int*)  d_in[20];
    float* out = (float*)d_out;

    // smem sizes
    const int SM512_256 = 512*36*4 + 256*33*8;   // 141312
    const int SM64_256  = 64*36*4  + 256*33*8;   //  76800
    const int SM512_128 = 512*36*4 + 128*33*8;   // 107520
    const int SM1024_128= 1024*36*4+ 128*33*8;   // 181248

    cudaFuncSetAttribute((const void*)g32<512,256,2,0,0,0>, cudaFuncAttributeMaxDynamicSharedMemorySize, SM512_256);
    cudaFuncSetAttribute((const void*)g32<64 ,256,2,0,0,1>, cudaFuncAttributeMaxDynamicSharedMemorySize, SM64_256);
    cudaFuncSetAttribute((const void*)g32<512,256,2,1,0,2>, cudaFuncAttributeMaxDynamicSharedMemorySize, SM512_256);
    cudaFuncSetAttribute((const void*)g32<512,32 ,8,3,1,3>, cudaFuncAttributeMaxDynamicSharedMemorySize, SM512_128);
    cudaFuncSetAttribute((const void*)g32<512,16,16,4,0,4>, cudaFuncAttributeMaxDynamicSharedMemorySize, SM512_128);
    cudaFuncSetAttribute((const void*)g32<1024,8,32,2,0,5>, cudaFuncAttributeMaxDynamicSharedMemorySize, SM1024_128);
    cudaFuncSetAttribute((const void*)g32<512,256,2,5,0,6>, cudaFuncAttributeMaxDynamicSharedMemorySize, SM512_256);

    // init state
    cudaMemcpyToSymbolAsync(g_hbuf, h0, 32*512*sizeof(float), 0, cudaMemcpyDeviceToDevice, 0);
    cudaMemcpyToSymbolAsync(g_cbuf, c0, 32*512*sizeof(float), 0, cudaMemcpyDeviceToDevice, 0);

    // precompute: phi_hs, phi_fds, ZX
    g32<512,256,2,0,0,0><<<dim3(2,100),256,SM512_256>>>(Wh, bh, enc, 512, out, 512, 0, lens, nullptr, nullptr);
    g32<64 ,256,2,0,0,1><<<dim3(2,100),256,SM64_256 >>>(Wf, bf, fld, 64 , out, 512, 0, lens, nullptr, nullptr);
    g32<512,256,2,1,0,2><<<dim3(8,65 ),256,SM512_256>>>(lW, lb, emb, 512, out, 2048, 0, lens, nullptr, inp);

    for (int t = 0; t < 65; t++) {
        // LSTM h-part GEMM + gates + state
        g32<512,32,8,3,1,3><<<dim3(64,1),128,SM512_128>>>(lW + (size_t)512*2048, lb, nullptr, 512, out, 2048, t, lens, nullptr, nullptr);
        // gamma (y=0) / alpha (y=1)
        g32<512,16,16,4,0,4><<<dim3(32,2),128,SM512_128>>>(Ws, bs, nullptr, 512, out, 512, t, lens, Wr, br);
        // attention
        attn_kernel<<<32,256>>>(enc);
        // att = tanh([ctx|ot] @ Wo + bo)
        g32<1024,8,32,2,0,5><<<dim3(64,1),128,SM1024_128>>>(Wo, bo, nullptr, 1024, out, 512, t, lens, nullptr, nullptr);
        // logits
        g32<512,256,2,5,0,6><<<dim3(125,1),256,SM512_256>>>(oW, ob, nullptr, 512, out, 32000, t, lens, nullptr, nullptr);
    }

    if (out_size >= 66560000 + 2*32*512)
        finalize_kernel<<<64,256>>>(out);
    (void)in_sizes; (void)n_in;
}